// round 7
// baseline (speedup 1.0000x reference)
#include <cuda_runtime.h>
#include <cuda_bf16.h>
#include <math.h>

#define NCTA    128
#define NTH     512
#define HDIM    2048
#define G3      6144      // 3*H
#define IDIM    512
#define ODIM    512
#define JPC     16        // h elements per CTA
#define ROWS_PC 48        // 3 gates * JPC
#define MAXL    4096

// ---- scratch (static device allocations are allowed) ----
__device__ __align__(256) float          g_A[(size_t)MAXL * G3];    // precomputed gi (+biases)
__device__ __align__(256) __nv_bfloat16  g_w16[(size_t)G3 * HDIM];  // enc_w_hh bf16, CTA-major
__device__ __align__(256) float          g_h[2][HDIM];              // double-buffered hidden state
__device__ __align__(256) float          g_logits[ODIM];
__device__ __align__(256) int            g_flags[NCTA];             // per-CTA epoch flags

__device__ __forceinline__ float warp_sum(float v) {
#pragma unroll
    for (int off = 16; off; off >>= 1) v += __shfl_xor_sync(0xffffffffu, v, off);
    return v;
}

__device__ __forceinline__ void flag_release(int* p, int v) {
    asm volatile("st.release.gpu.b32 [%0], %1;" :: "l"(p), "r"(v) : "memory");
}
__device__ __forceinline__ int flag_acquire(const int* p) {
    int v;
    asm volatile("ld.acquire.gpu.b32 %0, [%1];" : "=r"(v) : "l"(p) : "memory");
    return v;
}

// Contention-free grid barrier: each CTA release-stores its epoch to its own
// flag; 128 threads per CTA acquire-poll the 128 flags (coalesced), then bar.
__device__ __forceinline__ void grid_barrier(int epoch, int c, int tid) {
    __syncthreads();                       // all warps' stores of this step done
    if (tid == 0) flag_release(&g_flags[c], epoch);
    if (tid < NCTA) {
        while (flag_acquire(&g_flags[tid]) < epoch) { }
    }
    __syncthreads();
}

// ---------------------------------------------------------------------------
__global__ void k_init() {
    int i = blockIdx.x * blockDim.x + threadIdx.x;
    if (i < HDIM) { g_h[0][i] = 0.f; g_h[1][i] = 0.f; }
    if (i < NCTA) g_flags[i] = 0;
}

// enc_w_hh (fp32, row-major [6144][2048]) -> bf16, laid out per-CTA:
// dst[(c*48 + (g*16+w)) * 2048 + k] = whh[(g*2048 + c*16 + w) * 2048 + k]
__global__ void k_convert(const float* __restrict__ whh) {
    size_t idx = (size_t)blockIdx.x * blockDim.x + threadIdx.x;
    if (idx >= (size_t)G3 * HDIM) return;
    int k   = (int)(idx & (HDIM - 1));
    int lrc = (int)(idx >> 11);
    int c   = lrc / ROWS_PC;
    int lr  = lrc - c * ROWS_PC;
    int g   = lr >> 4;
    int w   = lr & 15;
    int row = g * HDIM + c * JPC + w;
    g_w16[idx] = __float2bfloat16(whh[(size_t)row * HDIM + k]);
}

// A[t, n] = sum_k X[t,k] * Wih[n,k] + b_ih[n] + (n < 2H ? b_hh[n] : 0)
__global__ void k_gemm(const float* __restrict__ X, const float* __restrict__ W,
                       const float* __restrict__ bih, const float* __restrict__ bhh,
                       int L) {
    __shared__ float As[16][65];
    __shared__ float Bs[16][65];
    int n0 = blockIdx.x * 64, t0 = blockIdx.y * 64;
    int tid = threadIdx.x;
    int tx = tid & 15, ty = tid >> 4;
    float acc[4][4];
#pragma unroll
    for (int i = 0; i < 4; i++)
#pragma unroll
        for (int jj = 0; jj < 4; jj++) acc[i][jj] = 0.f;

    for (int k0 = 0; k0 < IDIM; k0 += 16) {
#pragma unroll
        for (int i = 0; i < 4; i++) {
            int idx = tid + i * 256;
            int r = idx >> 4, cc = idx & 15;
            int t = t0 + r;
            As[cc][r] = (t < L) ? X[(size_t)t * IDIM + k0 + cc] : 0.f;
            Bs[cc][r] = W[(size_t)(n0 + r) * IDIM + k0 + cc];
        }
        __syncthreads();
#pragma unroll
        for (int kk = 0; kk < 16; kk++) {
            float a[4], b[4];
#pragma unroll
            for (int i = 0; i < 4; i++) a[i] = As[kk][ty * 4 + i];
#pragma unroll
            for (int jj = 0; jj < 4; jj++) b[jj] = Bs[kk][tx * 4 + jj];
#pragma unroll
            for (int i = 0; i < 4; i++)
#pragma unroll
                for (int jj = 0; jj < 4; jj++) acc[i][jj] = fmaf(a[i], b[jj], acc[i][jj]);
        }
        __syncthreads();
    }
#pragma unroll
    for (int i = 0; i < 4; i++) {
        int t = t0 + ty * 4 + i;
        if (t >= L) continue;
#pragma unroll
        for (int jj = 0; jj < 4; jj++) {
            int n = n0 + tx * 4 + jj;
            float v = acc[i][jj] + bih[n] + ((n < 2 * HDIM) ? bhh[n] : 0.f);
            g_A[(size_t)t * G3 + n] = v;
        }
    }
}

// ---------------------------------------------------------------------------
// Persistent RNN kernel: 128 CTAs (1/SM), 512 threads. Warp w of CTA c owns
// h element j = c*16 + w and its three gate rows (r, z, n).
__global__ void __launch_bounds__(NTH, 1)
k_rnn(const float* __restrict__ enc_bhh,
      const float* __restrict__ dwih, const float* __restrict__ dwhh,
      const float* __restrict__ dbih, const float* __restrict__ dbhh,
      const float* __restrict__ how,  const float* __restrict__ hob,
      float* __restrict__ out, int L, int T) {
    extern __shared__ unsigned short smw[];   // [48][2048] bf16 weights
    __shared__ float s_max, s_lse;
    __shared__ int   s_idx;

    const int c    = blockIdx.x;
    const int tid  = threadIdx.x;
    const int w    = tid >> 5;
    const int lane = tid & 31;
    const int j    = c * JPC + w;

    // load this CTA's encoder weight slice into shared memory
    {
        const uint4* src = reinterpret_cast<const uint4*>(g_w16 + (size_t)c * ROWS_PC * HDIM);
        uint4* dst = reinterpret_cast<uint4*>(smw);
        for (int i = tid; i < ROWS_PC * HDIM / 8; i += NTH) dst[i] = src[i];
    }

    float hreg[64];                       // h[k] for k = c8*256 + lane*8 + q
#pragma unroll
    for (int i = 0; i < 64; i++) hreg[i] = 0.f;
    float hold = 0.f;                     // lane0: current h[j]
    float bhn  = enc_bhh[2 * HDIM + j];   // used by lane0 only
    int epoch = 0;
    __syncthreads();

    // ---------------- encoder: L sequential GRU steps ----------------
    for (int t = 0; t < L; t++) {
        float Ar = 0.f, Az = 0.f, An = 0.f;
        if (lane == 0) {
            const float* Ab = g_A + (size_t)t * G3 + j;
            Ar = __ldg(Ab);
            Az = __ldg(Ab + HDIM);
            An = __ldg(Ab + 2 * HDIM);
        }
        float dots[3];
#pragma unroll
        for (int g = 0; g < 3; g++) {
            const unsigned short* wrow = smw + (size_t)(g * JPC + w) * HDIM;
            float a0 = 0.f, a1 = 0.f, a2 = 0.f, a3 = 0.f;
#pragma unroll
            for (int c8 = 0; c8 < 8; c8++) {
                uint4 p = *reinterpret_cast<const uint4*>(wrow + c8 * 256 + lane * 8);
                // bf16 -> fp32 by 16-bit shift/mask (pure ALU, dual-issues with FFMA)
                a0 = fmaf(__int_as_float(p.x << 16),         hreg[c8 * 8 + 0], a0);
                a1 = fmaf(__int_as_float(p.x & 0xffff0000u), hreg[c8 * 8 + 1], a1);
                a2 = fmaf(__int_as_float(p.y << 16),         hreg[c8 * 8 + 2], a2);
                a3 = fmaf(__int_as_float(p.y & 0xffff0000u), hreg[c8 * 8 + 3], a3);
                a0 = fmaf(__int_as_float(p.z << 16),         hreg[c8 * 8 + 4], a0);
                a1 = fmaf(__int_as_float(p.z & 0xffff0000u), hreg[c8 * 8 + 5], a1);
                a2 = fmaf(__int_as_float(p.w << 16),         hreg[c8 * 8 + 6], a2);
                a3 = fmaf(__int_as_float(p.w & 0xffff0000u), hreg[c8 * 8 + 7], a3);
            }
            dots[g] = warp_sum((a0 + a1) + (a2 + a3));
        }
        if (lane == 0) {
            float r = 1.f / (1.f + expf(-(dots[0] + Ar)));
            float z = 1.f / (1.f + expf(-(dots[1] + Az)));
            float n = tanhf(An + r * (dots[2] + bhn));
            hold = (1.f - z) * n + z * hold;
            g_h[(t + 1) & 1][j] = hold;
        }
        epoch++;
        grid_barrier(epoch, c, tid);
        // reload h into registers (L2-only loads: L1 is stale across CTAs)
        const float* hb = g_h[(t + 1) & 1];
#pragma unroll
        for (int c8 = 0; c8 < 8; c8++) {
            const float4* p = reinterpret_cast<const float4*>(hb + c8 * 256 + lane * 8);
            float4 v0 = __ldcg(p);
            float4 v1 = __ldcg(p + 1);
            hreg[c8 * 8 + 0] = v0.x; hreg[c8 * 8 + 1] = v0.y;
            hreg[c8 * 8 + 2] = v0.z; hreg[c8 * 8 + 3] = v0.w;
            hreg[c8 * 8 + 4] = v1.x; hreg[c8 * 8 + 5] = v1.y;
            hreg[c8 * 8 + 6] = v1.z; hreg[c8 * 8 + 7] = v1.w;
        }
    }

    // ---------------- autoregressive decoder ----------------
    float bir = 0.f, biz = 0.f, bin = 0.f, bhnd = 0.f;
    if (lane == 0) {
        bir  = dbih[j] + dbhh[j];
        biz  = dbih[HDIM + j] + dbhh[HDIM + j];
        bin  = dbih[2 * HDIM + j];
        bhnd = dbhh[2 * HDIM + j];
    }
    int idx = -1;   // one-hot index; -1 means zero input (first step)

    for (int s = 0; s < T; s++) {
        int par = (L + s) & 1;            // h currently lives in g_h[par]
        // --- phase A: GRU step (fp32 weights from L2) ---
        float dots[3];
#pragma unroll
        for (int g = 0; g < 3; g++) {
            const float* wrow = dwhh + (size_t)(g * HDIM + j) * HDIM;
            float a0 = 0.f, a1 = 0.f, a2 = 0.f, a3 = 0.f;
#pragma unroll
            for (int c8 = 0; c8 < 8; c8++) {
                const float4* p = reinterpret_cast<const float4*>(wrow + c8 * 256 + lane * 8);
                float4 v0 = __ldg(p);
                float4 v1 = __ldg(p + 1);
                a0 = fmaf(v0.x, hreg[c8 * 8 + 0], a0);
                a1 = fmaf(v0.y, hreg[c8 * 8 + 1], a1);
                a2 = fmaf(v0.z, hreg[c8 * 8 + 2], a2);
                a3 = fmaf(v0.w, hreg[c8 * 8 + 3], a3);
                a0 = fmaf(v1.x, hreg[c8 * 8 + 4], a0);
                a1 = fmaf(v1.y, hreg[c8 * 8 + 5], a1);
                a2 = fmaf(v1.z, hreg[c8 * 8 + 6], a2);
                a3 = fmaf(v1.w, hreg[c8 * 8 + 7], a3);
            }
            dots[g] = warp_sum((a0 + a1) + (a2 + a3));
        }
        if (lane == 0) {
            float gr = bir, gz = biz, gn = bin;
            if (idx >= 0) {   // one-hot input -> column gather of dec_w_ih
                gr += __ldg(dwih + (size_t)j * ODIM + idx);
                gz += __ldg(dwih + (size_t)(HDIM + j) * ODIM + idx);
                gn += __ldg(dwih + (size_t)(2 * HDIM + j) * ODIM + idx);
            }
            float r = 1.f / (1.f + expf(-(dots[0] + gr)));
            float z = 1.f / (1.f + expf(-(dots[1] + gz)));
            float n = tanhf(gn + r * (dots[2] + bhnd));
            hold = (1.f - z) * n + z * hold;
            g_h[par ^ 1][j] = hold;
        }
        epoch++;
        grid_barrier(epoch, c, tid);
        {
            const float* hb = g_h[par ^ 1];
#pragma unroll
            for (int c8 = 0; c8 < 8; c8++) {
                const float4* p = reinterpret_cast<const float4*>(hb + c8 * 256 + lane * 8);
                float4 v0 = __ldcg(p);
                float4 v1 = __ldcg(p + 1);
                hreg[c8 * 8 + 0] = v0.x; hreg[c8 * 8 + 1] = v0.y;
                hreg[c8 * 8 + 2] = v0.z; hreg[c8 * 8 + 3] = v0.w;
                hreg[c8 * 8 + 4] = v1.x; hreg[c8 * 8 + 5] = v1.y;
                hreg[c8 * 8 + 6] = v1.z; hreg[c8 * 8 + 7] = v1.w;
            }
        }
        // --- phase B: logits = h_new @ h2o_w^T + b (4 rows per CTA) ---
        float mylogit = 0.f;
        if (w < 4) {
            int row = c * 4 + w;
            const float* wrow = how + (size_t)row * HDIM;
            float a0 = 0.f, a1 = 0.f, a2 = 0.f, a3 = 0.f;
#pragma unroll
            for (int c8 = 0; c8 < 8; c8++) {
                const float4* p = reinterpret_cast<const float4*>(wrow + c8 * 256 + lane * 8);
                float4 v0 = __ldg(p);
                float4 v1 = __ldg(p + 1);
                a0 = fmaf(v0.x, hreg[c8 * 8 + 0], a0);
                a1 = fmaf(v0.y, hreg[c8 * 8 + 1], a1);
                a2 = fmaf(v0.z, hreg[c8 * 8 + 2], a2);
                a3 = fmaf(v0.w, hreg[c8 * 8 + 3], a3);
                a0 = fmaf(v1.x, hreg[c8 * 8 + 4], a0);
                a1 = fmaf(v1.y, hreg[c8 * 8 + 5], a1);
                a2 = fmaf(v1.z, hreg[c8 * 8 + 6], a2);
                a3 = fmaf(v1.w, hreg[c8 * 8 + 7], a3);
            }
            float acc = warp_sum((a0 + a1) + (a2 + a3));
            if (lane == 0) {
                mylogit = acc + __ldg(hob + row);
                g_logits[row] = mylogit;
            }
        }
        epoch++;
        grid_barrier(epoch, c, tid);
        // --- phase C: softmax stats + argmax (redundant per CTA, deterministic) ---
        if (w == 0) {
            float v[16];
#pragma unroll
            for (int q = 0; q < 16; q++) v[q] = __ldcg(g_logits + q * 32 + lane);
            float mx = v[0]; int mi = lane;
#pragma unroll
            for (int q = 1; q < 16; q++)
                if (v[q] > mx) { mx = v[q]; mi = q * 32 + lane; }
#pragma unroll
            for (int off = 16; off; off >>= 1) {
                float om = __shfl_xor_sync(0xffffffffu, mx, off);
                int   oi = __shfl_xor_sync(0xffffffffu, mi, off);
                if (om > mx || (om == mx && oi < mi)) { mx = om; mi = oi; }
            }
            float se = 0.f;
#pragma unroll
            for (int q = 0; q < 16; q++) se += expf(v[q] - mx);
            se = warp_sum(se);
            if (lane == 0) { s_max = mx; s_lse = logf(se); s_idx = mi; }
        }
        __syncthreads();
        idx = s_idx;
        if (w < 4 && lane == 0)
            out[(size_t)s * ODIM + c * 4 + w] = mylogit - s_max - s_lse;
        epoch++;
        grid_barrier(epoch, c, tid);   // protect g_logits reuse next step
    }
}

// ---------------------------------------------------------------------------
extern "C" void kernel_launch(void* const* d_in, const int* in_sizes, int n_in,
                              void* d_out, int out_size) {
    const float* input_   = (const float*)d_in[0];
    const float* enc_w_ih = (const float*)d_in[1];
    const float* enc_w_hh = (const float*)d_in[2];
    const float* enc_b_ih = (const float*)d_in[3];
    const float* enc_b_hh = (const float*)d_in[4];
    const float* dec_w_ih = (const float*)d_in[5];
    const float* dec_w_hh = (const float*)d_in[6];
    const float* dec_b_ih = (const float*)d_in[7];
    const float* dec_b_hh = (const float*)d_in[8];
    const float* h2o_w    = (const float*)d_in[9];
    const float* h2o_b    = (const float*)d_in[10];

    int L = in_sizes[0] / IDIM;
    if (L > MAXL) L = MAXL;
    int T = out_size / ODIM;

    // opt-in large dynamic shared memory (idempotent, not a stream op)
    cudaFuncSetAttribute(k_rnn, cudaFuncAttributeMaxDynamicSharedMemorySize,
                         ROWS_PC * HDIM * (int)sizeof(unsigned short));

    k_init<<<8, 256>>>();
    {
        size_t total = (size_t)G3 * HDIM;
        int grid = (int)((total + 255) / 256);
        k_convert<<<grid, 256>>>(enc_w_hh);
    }
    {
        dim3 gg(G3 / 64, (L + 63) / 64);
        k_gemm<<<gg, 256>>>(input_, enc_w_ih, enc_b_ih, enc_b_hh, L);
    }
    k_rnn<<<NCTA, NTH, ROWS_PC * HDIM * (int)sizeof(unsigned short)>>>(
        enc_b_hh, dec_w_ih, dec_w_hh, dec_b_ih, dec_b_hh,
        h2o_w, h2o_b, (float*)d_out, L, T);
}

// round 9
// speedup vs baseline: 1.6567x; 1.6567x over previous
#include <cuda_runtime.h>
#include <cuda_bf16.h>
#include <math.h>

#define NCTA    128
#define NTH     512
#define HDIM    2048
#define G3      6144      // 3*H
#define IDIM    512
#define ODIM    512
#define JPC     16        // h elements per CTA
#define ROWS_PC 48        // 3 gates * JPC
#define MAXL    4096
#define HSTRIDE 68        // padded SMEM h chunk stride (floats): 272B = 16 mod 128 -> conflict-free

// ---- scratch (static device allocations are allowed) ----
__device__ __align__(256) float          g_A[(size_t)MAXL * G3];    // precomputed gi (+biases)
__device__ __align__(256) __nv_bfloat16  g_w16[(size_t)G3 * HDIM];  // enc_w_hh bf16, permuted
__device__ __align__(256) float          g_h[2][HDIM];              // double-buffered hidden state
__device__ __align__(256) float          g_logits[ODIM];
__device__ __align__(256) int            g_flags[NCTA * 32];        // per-CTA flag, 128B stride
__device__ __align__(256) int            g_gen;

__device__ __forceinline__ float warp_sum(float v) {
#pragma unroll
    for (int off = 16; off; off >>= 1) v += __shfl_xor_sync(0xffffffffu, v, off);
    return v;
}

__device__ __forceinline__ void rel_store(int* p, int v) {
    asm volatile("st.release.gpu.b32 [%0], %1;" :: "l"(p), "r"(v) : "memory");
}
__device__ __forceinline__ int acq_load(const int* p) {
    int v;
    asm volatile("ld.acquire.gpu.b32 %0, [%1];" : "=r"(v) : "l"(p) : "memory");
    return v;
}

// Two-level grid barrier: CTAs release own padded flag; master (CTA 0)'s 128
// threads acquire-poll the flags, then release a generation word; one thread
// per other CTA acquire-polls gen. 255 total pollers, no same-line storms.
__device__ __forceinline__ void grid_barrier(int e, int c, int tid) {
    __syncthreads();                       // all warps' stores of this step done
    if (tid == 0) rel_store(&g_flags[c * 32], e);
    if (c == 0) {
        if (tid < NCTA) {
            while (acq_load(&g_flags[tid * 32]) < e) { }
        }
        __syncthreads();
        if (tid == 0) rel_store(&g_gen, e);
    } else {
        if (tid == 0) {
            while (acq_load(&g_gen) < e) { }
        }
        __syncthreads();                   // cumulativity spreads the acquire CTA-wide
    }
}

// ---------------------------------------------------------------------------
__global__ void k_init() {
    int i = blockIdx.x * blockDim.x + threadIdx.x;
    if (i < HDIM) { g_h[0][i] = 0.f; g_h[1][i] = 0.f; }
    if (i < NCTA * 32) g_flags[i] = 0;
    if (i == 0) g_gen = 0;
}

// enc_w_hh (fp32, [6144][2048]) -> bf16, permuted so that in-kernel position
// p = c8*256 + lane*8 + q maps to source column lane*64 + c8*8 + q, and rows
// are CTA-major: dst[(c*48 + g*16 + w)*2048 + p] = W[g*2048 + c*16 + w][col(p)]
__global__ void k_convert(const float* __restrict__ whh) {
    size_t idx = (size_t)blockIdx.x * blockDim.x + threadIdx.x;
    if (idx >= (size_t)G3 * HDIM) return;
    int p   = (int)(idx & (HDIM - 1));
    int lrc = (int)(idx >> 11);
    int c   = lrc / ROWS_PC;
    int lr  = lrc - c * ROWS_PC;
    int g   = lr >> 4;
    int w   = lr & 15;
    int row = g * HDIM + c * JPC + w;
    int col = ((p >> 3) & 31) * 64 + ((p >> 8) << 3) + (p & 7);
    g_w16[idx] = __float2bfloat16(whh[(size_t)row * HDIM + col]);
}

// A[t, n] = sum_k X[t,k] * Wih[n,k] + b_ih[n] + (n < 2H ? b_hh[n] : 0)
__global__ void k_gemm(const float* __restrict__ X, const float* __restrict__ W,
                       const float* __restrict__ bih, const float* __restrict__ bhh,
                       int L) {
    __shared__ float As[16][65];
    __shared__ float Bs[16][65];
    int n0 = blockIdx.x * 64, t0 = blockIdx.y * 64;
    int tid = threadIdx.x;
    int tx = tid & 15, ty = tid >> 4;
    float acc[4][4];
#pragma unroll
    for (int i = 0; i < 4; i++)
#pragma unroll
        for (int jj = 0; jj < 4; jj++) acc[i][jj] = 0.f;

    for (int k0 = 0; k0 < IDIM; k0 += 16) {
#pragma unroll
        for (int i = 0; i < 4; i++) {
            int idx = tid + i * 256;
            int r = idx >> 4, cc = idx & 15;
            int t = t0 + r;
            As[cc][r] = (t < L) ? X[(size_t)t * IDIM + k0 + cc] : 0.f;
            Bs[cc][r] = W[(size_t)(n0 + r) * IDIM + k0 + cc];
        }
        __syncthreads();
#pragma unroll
        for (int kk = 0; kk < 16; kk++) {
            float a[4], b[4];
#pragma unroll
            for (int i = 0; i < 4; i++) a[i] = As[kk][ty * 4 + i];
#pragma unroll
            for (int jj = 0; jj < 4; jj++) b[jj] = Bs[kk][tx * 4 + jj];
#pragma unroll
            for (int i = 0; i < 4; i++)
#pragma unroll
                for (int jj = 0; jj < 4; jj++) acc[i][jj] = fmaf(a[i], b[jj], acc[i][jj]);
        }
        __syncthreads();
    }
#pragma unroll
    for (int i = 0; i < 4; i++) {
        int t = t0 + ty * 4 + i;
        if (t >= L) continue;
#pragma unroll
        for (int jj = 0; jj < 4; jj++) {
            int n = n0 + tx * 4 + jj;
            float v = acc[i][jj] + bih[n] + ((n < 2 * HDIM) ? bhh[n] : 0.f);
            g_A[(size_t)t * G3 + n] = v;
        }
    }
}

// ---------------------------------------------------------------------------
// Persistent RNN kernel: 128 CTAs (1/SM), 512 threads. Warp w of CTA c owns
// h element j = c*16 + w. Lane `lane` owns h[lane*64 .. lane*64+63] in hreg.
__global__ void __launch_bounds__(NTH, 1)
k_rnn(const float* __restrict__ enc_bhh,
      const float* __restrict__ dwih, const float* __restrict__ dwhh,
      const float* __restrict__ dbih, const float* __restrict__ dbhh,
      const float* __restrict__ how,  const float* __restrict__ hob,
      float* __restrict__ out, int L, int T) {
    extern __shared__ unsigned short smw[];   // [48][2048] bf16 weights (permuted)
    float* smh = (float*)(smw + (size_t)ROWS_PC * HDIM);  // 32 chunks * 68 floats
    __shared__ float s_max, s_lse;
    __shared__ int   s_idx;

    const int c    = blockIdx.x;
    const int tid  = threadIdx.x;
    const int w    = tid >> 5;
    const int lane = tid & 31;
    const int j    = c * JPC + w;

    // load this CTA's encoder weight slice into shared memory
    {
        const uint4* src = reinterpret_cast<const uint4*>(g_w16 + (size_t)c * ROWS_PC * HDIM);
        uint4* dst = reinterpret_cast<uint4*>(smw);
        for (int i = tid; i < ROWS_PC * HDIM / 8; i += NTH) dst[i] = src[i];
    }

    float hreg[64];                       // hreg[i] = h[lane*64 + i]
#pragma unroll
    for (int i = 0; i < 64; i++) hreg[i] = 0.f;
    float hold = 0.f;                     // lane0: current h[j]
    float bhn  = enc_bhh[2 * HDIM + j];
    int epoch = 0;
    __syncthreads();

    // ---------------- encoder: L sequential GRU steps ----------------
    for (int t = 0; t < L; t++) {
        float Ar = 0.f, Az = 0.f, An = 0.f;
        if (lane == 0) {
            const float* Ab = g_A + (size_t)t * G3 + j;
            Ar = __ldg(Ab);
            Az = __ldg(Ab + HDIM);
            An = __ldg(Ab + 2 * HDIM);
        }
        float dots[3];
#pragma unroll
        for (int g = 0; g < 3; g++) {
            const unsigned short* wrow = smw + (size_t)(g * JPC + w) * HDIM;
            float a0 = 0.f, a1 = 0.f, a2 = 0.f, a3 = 0.f;
#pragma unroll
            for (int c8 = 0; c8 < 8; c8++) {
                uint4 p = *reinterpret_cast<const uint4*>(wrow + c8 * 256 + lane * 8);
                a0 = fmaf(__int_as_float(p.x << 16),         hreg[c8 * 8 + 0], a0);
                a1 = fmaf(__int_as_float(p.x & 0xffff0000u), hreg[c8 * 8 + 1], a1);
                a2 = fmaf(__int_as_float(p.y << 16),         hreg[c8 * 8 + 2], a2);
                a3 = fmaf(__int_as_float(p.y & 0xffff0000u), hreg[c8 * 8 + 3], a3);
                a0 = fmaf(__int_as_float(p.z << 16),         hreg[c8 * 8 + 4], a0);
                a1 = fmaf(__int_as_float(p.z & 0xffff0000u), hreg[c8 * 8 + 5], a1);
                a2 = fmaf(__int_as_float(p.w << 16),         hreg[c8 * 8 + 6], a2);
                a3 = fmaf(__int_as_float(p.w & 0xffff0000u), hreg[c8 * 8 + 7], a3);
            }
            dots[g] = warp_sum((a0 + a1) + (a2 + a3));
        }
        if (lane == 0) {
            float r = 1.f / (1.f + expf(-(dots[0] + Ar)));
            float z = 1.f / (1.f + expf(-(dots[1] + Az)));
            float n = tanhf(An + r * (dots[2] + bhn));
            hold = (1.f - z) * n + z * hold;
            g_h[(t + 1) & 1][j] = hold;
        }
        epoch++;
        grid_barrier(epoch, c, tid);
        // ONE 8KB L2 read per CTA -> SMEM (padded layout), then register fill
        {
            const float4 v = __ldcg(reinterpret_cast<const float4*>(g_h[(t + 1) & 1]) + tid);
            float* d = smh + (tid >> 4) * HSTRIDE + (tid & 15) * 4;
            *reinterpret_cast<float4*>(d) = v;
        }
        __syncthreads();
#pragma unroll
        for (int i4 = 0; i4 < 16; i4++) {
            float4 v = *reinterpret_cast<const float4*>(smh + lane * HSTRIDE + i4 * 4);
            hreg[i4 * 4 + 0] = v.x; hreg[i4 * 4 + 1] = v.y;
            hreg[i4 * 4 + 2] = v.z; hreg[i4 * 4 + 3] = v.w;
        }
    }

    // ---------------- autoregressive decoder ----------------
    float bir = 0.f, biz = 0.f, bin = 0.f, bhnd = 0.f;
    if (lane == 0) {
        bir  = dbih[j] + dbhh[j];
        biz  = dbih[HDIM + j] + dbhh[HDIM + j];
        bin  = dbih[2 * HDIM + j];
        bhnd = dbhh[2 * HDIM + j];
    }
    int idx = -1;   // one-hot index; -1 means zero input (first step)

    for (int s = 0; s < T; s++) {
        int par = (L + s) & 1;            // h currently lives in g_h[par]
        // --- phase A: GRU step (fp32 weights from L2; lane owns cols lane*64..) ---
        float dots[3];
#pragma unroll
        for (int g = 0; g < 3; g++) {
            const float* wrow = dwhh + (size_t)(g * HDIM + j) * HDIM;
            float a0 = 0.f, a1 = 0.f, a2 = 0.f, a3 = 0.f;
#pragma unroll
            for (int c8 = 0; c8 < 8; c8++) {
                const float4* p = reinterpret_cast<const float4*>(wrow + lane * 64 + c8 * 8);
                float4 v0 = __ldg(p);
                float4 v1 = __ldg(p + 1);
                a0 = fmaf(v0.x, hreg[c8 * 8 + 0], a0);
                a1 = fmaf(v0.y, hreg[c8 * 8 + 1], a1);
                a2 = fmaf(v0.z, hreg[c8 * 8 + 2], a2);
                a3 = fmaf(v0.w, hreg[c8 * 8 + 3], a3);
                a0 = fmaf(v1.x, hreg[c8 * 8 + 4], a0);
                a1 = fmaf(v1.y, hreg[c8 * 8 + 5], a1);
                a2 = fmaf(v1.z, hreg[c8 * 8 + 6], a2);
                a3 = fmaf(v1.w, hreg[c8 * 8 + 7], a3);
            }
            dots[g] = warp_sum((a0 + a1) + (a2 + a3));
        }
        if (lane == 0) {
            float gr = bir, gz = biz, gn = bin;
            if (idx >= 0) {   // one-hot input -> column gather of dec_w_ih
                gr += __ldg(dwih + (size_t)j * ODIM + idx);
                gz += __ldg(dwih + (size_t)(HDIM + j) * ODIM + idx);
                gn += __ldg(dwih + (size_t)(2 * HDIM + j) * ODIM + idx);
            }
            float r = 1.f / (1.f + expf(-(dots[0] + gr)));
            float z = 1.f / (1.f + expf(-(dots[1] + gz)));
            float n = tanhf(gn + r * (dots[2] + bhnd));
            hold = (1.f - z) * n + z * hold;
            g_h[par ^ 1][j] = hold;
        }
        epoch++;
        grid_barrier(epoch, c, tid);
        {
            const float4 v = __ldcg(reinterpret_cast<const float4*>(g_h[par ^ 1]) + tid);
            float* d = smh + (tid >> 4) * HSTRIDE + (tid & 15) * 4;
            *reinterpret_cast<float4*>(d) = v;
        }
        __syncthreads();
#pragma unroll
        for (int i4 = 0; i4 < 16; i4++) {
            float4 v = *reinterpret_cast<const float4*>(smh + lane * HSTRIDE + i4 * 4);
            hreg[i4 * 4 + 0] = v.x; hreg[i4 * 4 + 1] = v.y;
            hreg[i4 * 4 + 2] = v.z; hreg[i4 * 4 + 3] = v.w;
        }
        // --- phase B: logits = h_new @ h2o_w^T + b (4 rows per CTA) ---
        float mylogit = 0.f;
        if (w < 4) {
            int row = c * 4 + w;
            const float* wrow = how + (size_t)row * HDIM;
            float a0 = 0.f, a1 = 0.f, a2 = 0.f, a3 = 0.f;
#pragma unroll
            for (int c8 = 0; c8 < 8; c8++) {
                const float4* p = reinterpret_cast<const float4*>(wrow + lane * 64 + c8 * 8);
                float4 v0 = __ldg(p);
                float4 v1 = __ldg(p + 1);
                a0 = fmaf(v0.x, hreg[c8 * 8 + 0], a0);
                a1 = fmaf(v0.y, hreg[c8 * 8 + 1], a1);
                a2 = fmaf(v0.z, hreg[c8 * 8 + 2], a2);
                a3 = fmaf(v0.w, hreg[c8 * 8 + 3], a3);
                a0 = fmaf(v1.x, hreg[c8 * 8 + 4], a0);
                a1 = fmaf(v1.y, hreg[c8 * 8 + 5], a1);
                a2 = fmaf(v1.z, hreg[c8 * 8 + 6], a2);
                a3 = fmaf(v1.w, hreg[c8 * 8 + 7], a3);
            }
            float acc = warp_sum((a0 + a1) + (a2 + a3));
            if (lane == 0) {
                mylogit = acc + __ldg(hob + row);
                g_logits[row] = mylogit;
            }
        }
        epoch++;
        grid_barrier(epoch, c, tid);
        // --- phase C: softmax stats + argmax (redundant per CTA, deterministic) ---
        if (w == 0) {
            float v[16];
#pragma unroll
            for (int q = 0; q < 16; q++) v[q] = __ldcg(g_logits + q * 32 + lane);
            float mx = v[0]; int mi = lane;
#pragma unroll
            for (int q = 1; q < 16; q++)
                if (v[q] > mx) { mx = v[q]; mi = q * 32 + lane; }
#pragma unroll
            for (int off = 16; off; off >>= 1) {
                float om = __shfl_xor_sync(0xffffffffu, mx, off);
                int   oi = __shfl_xor_sync(0xffffffffu, mi, off);
                if (om > mx || (om == mx && oi < mi)) { mx = om; mi = oi; }
            }
            float se = 0.f;
#pragma unroll
            for (int q = 0; q < 16; q++) se += expf(v[q] - mx);
            se = warp_sum(se);
            if (lane == 0) { s_max = mx; s_lse = logf(se); s_idx = mi; }
        }
        __syncthreads();
        idx = s_idx;
        if (w < 4 && lane == 0)
            out[(size_t)s * ODIM + c * 4 + w] = mylogit - s_max - s_lse;
        epoch++;
        grid_barrier(epoch, c, tid);   // protect g_logits reuse next step
    }
}

// ---------------------------------------------------------------------------
extern "C" void kernel_launch(void* const* d_in, const int* in_sizes, int n_in,
                              void* d_out, int out_size) {
    const float* input_   = (const float*)d_in[0];
    const float* enc_w_ih = (const float*)d_in[1];
    const float* enc_w_hh = (const float*)d_in[2];
    const float* enc_b_ih = (const float*)d_in[3];
    const float* enc_b_hh = (const float*)d_in[4];
    const float* dec_w_ih = (const float*)d_in[5];
    const float* dec_w_hh = (const float*)d_in[6];
    const float* dec_b_ih = (const float*)d_in[7];
    const float* dec_b_hh = (const float*)d_in[8];
    const float* h2o_w    = (const float*)d_in[9];
    const float* h2o_b    = (const float*)d_in[10];

    int L = in_sizes[0] / IDIM;
    if (L > MAXL) L = MAXL;
    int T = out_size / ODIM;

    const int dyn_smem = ROWS_PC * HDIM * (int)sizeof(unsigned short)
                       + 32 * HSTRIDE * (int)sizeof(float);
    cudaFuncSetAttribute(k_rnn, cudaFuncAttributeMaxDynamicSharedMemorySize, dyn_smem);

    k_init<<<16, 256>>>();
    {
        size_t total = (size_t)G3 * HDIM;
        int grid = (int)((total + 255) / 256);
        k_convert<<<grid, 256>>>(enc_w_hh);
    }
    {
        dim3 gg(G3 / 64, (L + 63) / 64);
        k_gemm<<<gg, 256>>>(input_, enc_w_ih, enc_b_ih, enc_b_hh, L);
    }
    k_rnn<<<NCTA, NTH, dyn_smem>>>(
        enc_b_hh, dec_w_ih, dec_w_hh, dec_b_ih, dec_b_hh,
        h2o_w, h2o_b, (float*)d_out, L, T);
}

// round 13
// speedup vs baseline: 1.9501x; 1.1771x over previous
#include <cuda_runtime.h>
#include <cuda_bf16.h>
#include <math.h>

#define NCTA    128
#define NTH     1024
#define HDIM    2048
#define G3      6144      // 3*H
#define IDIM    512
#define ODIM    512
#define JPC     16        // h elements per CTA
#define ROWS_PC 48        // 3 gates * JPC
#define MAXL    4096
#define HSTRIDE 68        // padded SMEM h chunk stride (floats)

// ---- scratch (static device allocations are allowed) ----
__device__ __align__(256) float          g_A[(size_t)MAXL * G3];    // precomputed gi (+biases)
__device__ __align__(256) __nv_bfloat16  g_w16[(size_t)G3 * HDIM];  // enc_w_hh bf16, permuted
__device__ __align__(256) float          g_h[2][HDIM];              // double-buffered hidden state
__device__ __align__(256) float          g_logits[ODIM];
__device__ __align__(256) int            g_flags[NCTA * 32];        // per-CTA flag, 128B stride

__device__ __forceinline__ float warp_sum(float v) {
#pragma unroll
    for (int off = 16; off; off >>= 1) v += __shfl_xor_sync(0xffffffffu, v, off);
    return v;
}

__device__ __forceinline__ void rel_store(int* p, int v) {
    asm volatile("st.release.gpu.b32 [%0], %1;" :: "l"(p), "r"(v) : "memory");
}
__device__ __forceinline__ int acq_load(const int* p) {
    int v;
    asm volatile("ld.acquire.gpu.b32 %0, [%1];" : "=r"(v) : "l"(p) : "memory");
    return v;
}

__device__ __forceinline__ float fast_sigmoid(float x) {
    return __fdividef(1.f, 1.f + __expf(-x));
}
__device__ __forceinline__ float fast_tanh(float x) {
    return __fdividef(2.f, 1.f + __expf(-2.f * x)) - 1.f;
}

// Flat one-level grid barrier: each CTA release-stores its own padded flag;
// warp 0 of EVERY CTA polls all 128 flags (4 per lane). One L2 hop.
__device__ __forceinline__ void grid_barrier(int e, int c, int tid, int lane) {
    __syncthreads();                       // all pre-barrier stores issued
    if (tid == 0) rel_store(&g_flags[c * 32], e);
    if (tid < 32) {
        const int f0 = lane * 4;
        bool ok;
        do {
            int a = acq_load(&g_flags[(f0 + 0) * 32]);
            int b = acq_load(&g_flags[(f0 + 1) * 32]);
            int d = acq_load(&g_flags[(f0 + 2) * 32]);
            int f = acq_load(&g_flags[(f0 + 3) * 32]);
            ok = (a >= e) && (b >= e) && (d >= e) && (f >= e);
        } while (!__all_sync(0xffffffffu, ok));
    }
    __syncthreads();                       // barrier ordering spreads acquire CTA-wide
}

// ---------------------------------------------------------------------------
__global__ void k_init() {
    int i = blockIdx.x * blockDim.x + threadIdx.x;
    if (i < HDIM) { g_h[0][i] = 0.f; g_h[1][i] = 0.f; }
    if (i < NCTA * 32) g_flags[i] = 0;
}

// enc_w_hh (fp32, [6144][2048]) -> bf16, permuted: position p in row maps to
// source column col(p) = ((p>>3)&31)*64 + ((p>>8)<<3) + (p&7); rows CTA-major.
__global__ void k_convert(const float* __restrict__ whh) {
    size_t idx = (size_t)blockIdx.x * blockDim.x + threadIdx.x;
    if (idx >= (size_t)G3 * HDIM) return;
    int p   = (int)(idx & (HDIM - 1));
    int lrc = (int)(idx >> 11);
    int c   = lrc / ROWS_PC;
    int lr  = lrc - c * ROWS_PC;
    int g   = lr >> 4;
    int w   = lr & 15;
    int row = g * HDIM + c * JPC + w;
    int col = ((p >> 3) & 31) * 64 + ((p >> 8) << 3) + (p & 7);
    g_w16[idx] = __float2bfloat16(whh[(size_t)row * HDIM + col]);
}

// A[t, n] = sum_k X[t,k] * Wih[n,k] + b_ih[n] + (n < 2H ? b_hh[n] : 0)
__global__ void k_gemm(const float* __restrict__ X, const float* __restrict__ W,
                       const float* __restrict__ bih, const float* __restrict__ bhh,
                       int L) {
    __shared__ float As[16][65];
    __shared__ float Bs[16][65];
    int n0 = blockIdx.x * 64, t0 = blockIdx.y * 64;
    int tid = threadIdx.x;
    int tx = tid & 15, ty = tid >> 4;
    float acc[4][4];
#pragma unroll
    for (int i = 0; i < 4; i++)
#pragma unroll
        for (int jj = 0; jj < 4; jj++) acc[i][jj] = 0.f;

    for (int k0 = 0; k0 < IDIM; k0 += 16) {
#pragma unroll
        for (int i = 0; i < 4; i++) {
            int idx = tid + i * 256;
            int r = idx >> 4, cc = idx & 15;
            int t = t0 + r;
            As[cc][r] = (t < L) ? X[(size_t)t * IDIM + k0 + cc] : 0.f;
            Bs[cc][r] = W[(size_t)(n0 + r) * IDIM + k0 + cc];
        }
        __syncthreads();
#pragma unroll
        for (int kk = 0; kk < 16; kk++) {
            float a[4], b[4];
#pragma unroll
            for (int i = 0; i < 4; i++) a[i] = As[kk][ty * 4 + i];
#pragma unroll
            for (int jj = 0; jj < 4; jj++) b[jj] = Bs[kk][tx * 4 + jj];
#pragma unroll
            for (int i = 0; i < 4; i++)
#pragma unroll
                for (int jj = 0; jj < 4; jj++) acc[i][jj] = fmaf(a[i], b[jj], acc[i][jj]);
        }
        __syncthreads();
    }
#pragma unroll
    for (int i = 0; i < 4; i++) {
        int t = t0 + ty * 4 + i;
        if (t >= L) continue;
#pragma unroll
        for (int jj = 0; jj < 4; jj++) {
            int n = n0 + tx * 4 + jj;
            float v = acc[i][jj] + bih[n] + ((n < 2 * HDIM) ? bhh[n] : 0.f);
            g_A[(size_t)t * G3 + n] = v;
        }
    }
}

// ---------------------------------------------------------------------------
// Persistent RNN kernel: 128 CTAs (1/SM), 1024 threads (32 warps). Warp pair
// (wr, wr+16) owns h element j = c*16 + wr; warp half hf covers h-columns
// lane*64 + hf*32 .. +31. hreg[i] = h[lane*64 + hf*32 + i].
__global__ void __launch_bounds__(NTH, 1)
k_rnn(const float* __restrict__ enc_bhh,
      const float* __restrict__ dwih, const float* __restrict__ dwhh,
      const float* __restrict__ dbih, const float* __restrict__ dbhh,
      const float* __restrict__ how,  const float* __restrict__ hob,
      float* __restrict__ out, int L, int T) {
    extern __shared__ unsigned short smw[];   // [48][2048] bf16 weights (permuted)
    float* smh = (float*)(smw + (size_t)ROWS_PC * HDIM);  // 32 chunks * 68 floats
    __shared__ float sPart[2][16][3];
    __shared__ float s_max, s_lse;
    __shared__ int   s_idx;

    const int c    = blockIdx.x;
    const int tid  = threadIdx.x;
    const int w    = tid >> 5;
    const int lane = tid & 31;
    const int wr   = w & 15;     // row group
    const int hf   = w >> 4;     // which half of h this warp covers
    const int j    = c * JPC + wr;

    // load this CTA's encoder weight slice into shared memory
    {
        const uint4* src = reinterpret_cast<const uint4*>(g_w16 + (size_t)c * ROWS_PC * HDIM);
        uint4* dst = reinterpret_cast<uint4*>(smw);
        for (int i = tid; i < ROWS_PC * HDIM / 8; i += NTH) dst[i] = src[i];
    }

    float hreg[32];
#pragma unroll
    for (int i = 0; i < 32; i++) hreg[i] = 0.f;
    float hold = 0.f;                     // low-warp lane0: current h[j]
    float bhn  = enc_bhh[2 * HDIM + j];
    int epoch = 0;
    __syncthreads();

    // ---------------- encoder: L sequential GRU steps ----------------
    for (int t = 0; t < L; t++) {
        float Ar = 0.f, Az = 0.f, An = 0.f;
        if (hf == 0 && lane == 0) {
            const float* Ab = g_A + (size_t)t * G3 + j;
            Ar = __ldg(Ab);
            Az = __ldg(Ab + HDIM);
            An = __ldg(Ab + 2 * HDIM);
        }
        const unsigned short* wbase = smw + hf * 1024;
#pragma unroll
        for (int g = 0; g < 3; g++) {
            const unsigned short* wrow = wbase + (size_t)(g * JPC + wr) * HDIM;
            float a0 = 0.f, a1 = 0.f, a2 = 0.f, a3 = 0.f;
#pragma unroll
            for (int c8 = 0; c8 < 4; c8++) {
                uint4 p = *reinterpret_cast<const uint4*>(wrow + c8 * 256 + lane * 8);
                a0 = fmaf(__int_as_float(p.x << 16),         hreg[c8 * 8 + 0], a0);
                a1 = fmaf(__int_as_float(p.x & 0xffff0000u), hreg[c8 * 8 + 1], a1);
                a2 = fmaf(__int_as_float(p.y << 16),         hreg[c8 * 8 + 2], a2);
                a3 = fmaf(__int_as_float(p.y & 0xffff0000u), hreg[c8 * 8 + 3], a3);
                a0 = fmaf(__int_as_float(p.z << 16),         hreg[c8 * 8 + 4], a0);
                a1 = fmaf(__int_as_float(p.z & 0xffff0000u), hreg[c8 * 8 + 5], a1);
                a2 = fmaf(__int_as_float(p.w << 16),         hreg[c8 * 8 + 6], a2);
                a3 = fmaf(__int_as_float(p.w & 0xffff0000u), hreg[c8 * 8 + 7], a3);
            }
            float s = warp_sum((a0 + a1) + (a2 + a3));
            if (lane == 0) sPart[hf][wr][g] = s;
        }
        __syncthreads();
        if (hf == 0 && lane == 0) {
            float dr = sPart[0][wr][0] + sPart[1][wr][0];
            float dz = sPart[0][wr][1] + sPart[1][wr][1];
            float dn = sPart[0][wr][2] + sPart[1][wr][2];
            float r = fast_sigmoid(dr + Ar);
            float z = fast_sigmoid(dz + Az);
            float n = fast_tanh(An + r * (dn + bhn));
            hold = (1.f - z) * n + z * hold;
            g_h[(t + 1) & 1][j] = hold;
        }
        epoch++;
        grid_barrier(epoch, c, tid, lane);
        // one 8KB L2 read per CTA -> SMEM staging -> register fill (half per warp)
        if (tid < 512) {
            const float4 v = __ldcg(reinterpret_cast<const float4*>(g_h[(t + 1) & 1]) + tid);
            float* d = smh + (tid >> 4) * HSTRIDE + (tid & 15) * 4;
            *reinterpret_cast<float4*>(d) = v;
        }
        __syncthreads();
#pragma unroll
        for (int i4 = 0; i4 < 8; i4++) {
            float4 v = *reinterpret_cast<const float4*>(smh + lane * HSTRIDE + hf * 32 + i4 * 4);
            hreg[i4 * 4 + 0] = v.x; hreg[i4 * 4 + 1] = v.y;
            hreg[i4 * 4 + 2] = v.z; hreg[i4 * 4 + 3] = v.w;
        }
    }

    // ---------------- autoregressive decoder ----------------
    float bir = 0.f, biz = 0.f, bin = 0.f, bhnd = 0.f;
    if (hf == 0 && lane == 0) {
        bir  = dbih[j] + dbhh[j];
        biz  = dbih[HDIM + j] + dbhh[HDIM + j];
        bin  = dbih[2 * HDIM + j];
        bhnd = dbhh[2 * HDIM + j];
    }
    int idx = -1;   // one-hot index; -1 means zero input (first step)

    for (int s = 0; s < T; s++) {
        int par = (L + s) & 1;            // h currently lives in g_h[par]
        // --- phase A: GRU step (fp32 weights from L2, split halves) ---
#pragma unroll
        for (int g = 0; g < 3; g++) {
            const float* wrow = dwhh + (size_t)(g * HDIM + j) * HDIM + hf * 32;
            float a0 = 0.f, a1 = 0.f, a2 = 0.f, a3 = 0.f;
#pragma unroll
            for (int c8 = 0; c8 < 4; c8++) {
                const float4* p = reinterpret_cast<const float4*>(wrow + lane * 64 + c8 * 8);
                float4 v0 = __ldg(p);
                float4 v1 = __ldg(p + 1);
                a0 = fmaf(v0.x, hreg[c8 * 8 + 0], a0);
                a1 = fmaf(v0.y, hreg[c8 * 8 + 1], a1);
                a2 = fmaf(v0.z, hreg[c8 * 8 + 2], a2);
                a3 = fmaf(v0.w, hreg[c8 * 8 + 3], a3);
                a0 = fmaf(v1.x, hreg[c8 * 8 + 4], a0);
                a1 = fmaf(v1.y, hreg[c8 * 8 + 5], a1);
                a2 = fmaf(v1.z, hreg[c8 * 8 + 6], a2);
                a3 = fmaf(v1.w, hreg[c8 * 8 + 7], a3);
            }
            float ssum = warp_sum((a0 + a1) + (a2 + a3));
            if (lane == 0) sPart[hf][wr][g] = ssum;
        }
        __syncthreads();
        if (hf == 0 && lane == 0) {
            float gr = bir, gz = biz, gn = bin;
            if (idx >= 0) {   // one-hot input -> column gather of dec_w_ih
                gr += __ldg(dwih + (size_t)j * ODIM + idx);
                gz += __ldg(dwih + (size_t)(HDIM + j) * ODIM + idx);
                gn += __ldg(dwih + (size_t)(2 * HDIM + j) * ODIM + idx);
            }
            float dr = sPart[0][wr][0] + sPart[1][wr][0];
            float dz = sPart[0][wr][1] + sPart[1][wr][1];
            float dn = sPart[0][wr][2] + sPart[1][wr][2];
            float r = fast_sigmoid(dr + gr);
            float z = fast_sigmoid(dz + gz);
            float n = fast_tanh(gn + r * (dn + bhnd));
            hold = (1.f - z) * n + z * hold;
            g_h[par ^ 1][j] = hold;
        }
        epoch++;
        grid_barrier(epoch, c, tid, lane);
        if (tid < 512) {
            const float4 v = __ldcg(reinterpret_cast<const float4*>(g_h[par ^ 1]) + tid);
            float* d = smh + (tid >> 4) * HSTRIDE + (tid & 15) * 4;
            *reinterpret_cast<float4*>(d) = v;
        }
        __syncthreads();
#pragma unroll
        for (int i4 = 0; i4 < 8; i4++) {
            float4 v = *reinterpret_cast<const float4*>(smh + lane * HSTRIDE + hf * 32 + i4 * 4);
            hreg[i4 * 4 + 0] = v.x; hreg[i4 * 4 + 1] = v.y;
            hreg[i4 * 4 + 2] = v.z; hreg[i4 * 4 + 3] = v.w;
        }
        // --- phase B: logits = h_new @ h2o_w^T + b (4 rows/CTA, warps 0-3,
        //     full h read from SMEM staging) ---
        float mylogit = 0.f;
        if (w < 4) {
            int row = c * 4 + w;
            const float* wrow = how + (size_t)row * HDIM;
            float a0 = 0.f, a1 = 0.f, a2 = 0.f, a3 = 0.f;
#pragma unroll
            for (int c8 = 0; c8 < 8; c8++) {
                const float4* p = reinterpret_cast<const float4*>(wrow + lane * 64 + c8 * 8);
                float4 v0 = __ldg(p);
                float4 v1 = __ldg(p + 1);
                const float* hp = smh + lane * HSTRIDE + c8 * 8;
                float4 h0 = *reinterpret_cast<const float4*>(hp);
                float4 h1 = *reinterpret_cast<const float4*>(hp + 4);
                a0 = fmaf(v0.x, h0.x, a0);
                a1 = fmaf(v0.y, h0.y, a1);
                a2 = fmaf(v0.z, h0.z, a2);
                a3 = fmaf(v0.w, h0.w, a3);
                a0 = fmaf(v1.x, h1.x, a0);
                a1 = fmaf(v1.y, h1.y, a1);
                a2 = fmaf(v1.z, h1.z, a2);
                a3 = fmaf(v1.w, h1.w, a3);
            }
            float acc = warp_sum((a0 + a1) + (a2 + a3));
            if (lane == 0) {
                mylogit = acc + __ldg(hob + row);
                g_logits[row] = mylogit;
            }
        }
        epoch++;
        grid_barrier(epoch, c, tid, lane);
        // --- phase C: softmax stats + argmax (redundant per CTA, deterministic) ---
        if (w == 0) {
            float v[16];
#pragma unroll
            for (int q = 0; q < 16; q++) v[q] = __ldcg(g_logits + q * 32 + lane);
            float mx = v[0]; int mi = lane;
#pragma unroll
            for (int q = 1; q < 16; q++)
                if (v[q] > mx) { mx = v[q]; mi = q * 32 + lane; }
#pragma unroll
            for (int off = 16; off; off >>= 1) {
                float om = __shfl_xor_sync(0xffffffffu, mx, off);
                int   oi = __shfl_xor_sync(0xffffffffu, mi, off);
                if (om > mx || (om == mx && oi < mi)) { mx = om; mi = oi; }
            }
            float se = 0.f;
#pragma unroll
            for (int q = 0; q < 16; q++) se += expf(v[q] - mx);
            se = warp_sum(se);
            if (lane == 0) { s_max = mx; s_lse = logf(se); s_idx = mi; }
        }
        __syncthreads();
        idx = s_idx;
        if (w < 4 && lane == 0)
            out[(size_t)s * ODIM + c * 4 + w] = mylogit - s_max - s_lse;
        epoch++;
        grid_barrier(epoch, c, tid, lane);   // protect g_logits reuse next step
    }
}

// ---------------------------------------------------------------------------
extern "C" void kernel_launch(void* const* d_in, const int* in_sizes, int n_in,
                              void* d_out, int out_size) {
    const float* input_   = (const float*)d_in[0];
    const float* enc_w_ih = (const float*)d_in[1];
    const float* enc_w_hh = (const float*)d_in[2];
    const float* enc_b_ih = (const float*)d_in[3];
    const float* enc_b_hh = (const float*)d_in[4];
    const float* dec_w_ih = (const float*)d_in[5];
    const float* dec_w_hh = (const float*)d_in[6];
    const float* dec_b_ih = (const float*)d_in[7];
    const float* dec_b_hh = (const float*)d_in[8];
    const float* h2o_w    = (const float*)d_in[9];
    const float* h2o_b    = (const float*)d_in[10];

    int L = in_sizes[0] / IDIM;
    if (L > MAXL) L = MAXL;
    int T = out_size / ODIM;

    const int dyn_smem = ROWS_PC * HDIM * (int)sizeof(unsigned short)
                       + 32 * HSTRIDE * (int)sizeof(float);
    cudaFuncSetAttribute(k_rnn, cudaFuncAttributeMaxDynamicSharedMemorySize, dyn_smem);

    k_init<<<16, 256>>>();
    {
        size_t total = (size_t)G3 * HDIM;
        int grid = (int)((total + 255) / 256);
        k_convert<<<grid, 256>>>(enc_w_hh);
    }
    {
        dim3 gg(G3 / 64, (L + 63) / 64);
        k_gemm<<<gg, 256>>>(input_, enc_w_ih, enc_b_ih, enc_b_hh, L);
    }
    k_rnn<<<NCTA, NTH, dyn_smem>>>(
        enc_b_hh, dec_w_ih, dec_w_hh, dec_b_ih, dec_b_hh,
        h2o_w, h2o_b, (float*)d_out, L, T);
}

// round 17
// speedup vs baseline: 2.1682x; 1.1118x over previous
#include <cuda_runtime.h>
#include <cuda_bf16.h>
#include <math.h>

#define NCTA    128
#define NTH     1024
#define HDIM    2048
#define G3      6144      // 3*H
#define IDIM    512
#define ODIM    512
#define JPC     16        // h elements per CTA
#define ROWS_PC 48        // 3 gates * JPC
#define MAXL    4096
#define HSTRIDE 68        // padded SMEM h chunk stride (floats)

// One 128B line per CTA: 16 h floats + epoch flag in the SAME cache line.
struct __align__(128) PubLine { float h[16]; int epoch; int pad[15]; };

// ---- scratch (static device allocations are allowed) ----
__device__ __align__(256) float          g_A[(size_t)MAXL * G3];    // precomputed gi (+biases)
__device__ __align__(256) __nv_bfloat16  g_w16[(size_t)G3 * HDIM];  // enc_w_hh bf16, permuted
__device__ PubLine                       g_pub[2][NCTA];            // parity-buffered h lines
__device__ __align__(256) float          g_logits[ODIM];
__device__ __align__(256) int            g_flags[NCTA * 32];        // per-CTA flag, 128B stride

__device__ __forceinline__ float warp_sum(float v) {
#pragma unroll
    for (int off = 16; off; off >>= 1) v += __shfl_xor_sync(0xffffffffu, v, off);
    return v;
}

__device__ __forceinline__ void rel_store(int* p, int v) {
    asm volatile("st.release.gpu.b32 [%0], %1;" :: "l"(p), "r"(v) : "memory");
}
__device__ __forceinline__ int acq_load(const int* p) {
    int v;
    asm volatile("ld.acquire.gpu.b32 %0, [%1];" : "=r"(v) : "l"(p) : "memory");
    return v;
}

__device__ __forceinline__ float fast_sigmoid(float x) {
    return __fdividef(1.f, 1.f + __expf(-x));
}
__device__ __forceinline__ float fast_tanh(float x) {
    return __fdividef(2.f, 1.f + __expf(-2.f * x)) - 1.f;
}

// ---- f32x2 packed math helpers ----
__device__ __forceinline__ unsigned long long pack2(float a, float b) {
    unsigned long long r;
    asm("mov.b64 %0, {%1, %2};" : "=l"(r) : "f"(a), "f"(b));
    return r;
}
__device__ __forceinline__ float2 unpack2(unsigned long long a) {
    float x, y;
    asm("mov.b64 {%0, %1}, %2;" : "=f"(x), "=f"(y) : "l"(a));
    return make_float2(x, y);
}
__device__ __forceinline__ unsigned long long ffma2(unsigned long long a,
                                                    unsigned long long b,
                                                    unsigned long long c) {
    unsigned long long d;
    asm("fma.rn.f32x2 %0, %1, %2, %3;" : "=l"(d) : "l"(a), "l"(b), "l"(c));
    return d;
}
// two bf16 in a u32 -> f32x2 pair {lo, hi}
__device__ __forceinline__ unsigned long long bf16pair(unsigned int x) {
    unsigned int lo = x << 16;
    unsigned int hi = x & 0xffff0000u;
    unsigned long long r;
    asm("mov.b64 %0, {%1, %2};" : "=l"(r) : "r"(lo), "r"(hi));
    return r;
}

// Flat flag barrier (decoder phases B/C): warp 0 polls all 128 flags.
__device__ __forceinline__ void grid_barrier(int e, int c, int tid, int lane) {
    __syncthreads();
    if (tid == 0) rel_store(&g_flags[c * 32], e);
    if (tid < 32) {
        const int f0 = lane * 4;
        bool ok;
        do {
            int a = acq_load(&g_flags[(f0 + 0) * 32]);
            int b = acq_load(&g_flags[(f0 + 1) * 32]);
            int d = acq_load(&g_flags[(f0 + 2) * 32]);
            int f = acq_load(&g_flags[(f0 + 3) * 32]);
            ok = (a >= e) && (b >= e) && (d >= e) && (f >= e);
        } while (!__all_sync(0xffffffffu, ok));
    }
    __syncthreads();
}

// Publish-barrier: CTA's 16 new h values (already in sGate) go out in ONE
// 128B line with the epoch; 128 pollers each own a line, and on flag pass
// read the h data from the same hot L2 line straight into SMEM staging.
__device__ __forceinline__ void publish_barrier(int e, int c, int tid,
                                                float* smh, const float* sGate) {
    __syncthreads();                        // sGate complete; smh free
    if (tid == 0) {
        PubLine* my = &g_pub[e & 1][c];
        *reinterpret_cast<float4*>(&my->h[0])  = *reinterpret_cast<const float4*>(&sGate[0]);
        *reinterpret_cast<float4*>(&my->h[4])  = *reinterpret_cast<const float4*>(&sGate[4]);
        *reinterpret_cast<float4*>(&my->h[8])  = *reinterpret_cast<const float4*>(&sGate[8]);
        *reinterpret_cast<float4*>(&my->h[12]) = *reinterpret_cast<const float4*>(&sGate[12]);
        rel_store(&my->epoch, e);           // release orders the h stores before the flag
    }
    if (tid < NCTA) {
        PubLine* ln = &g_pub[e & 1][tid];
        while (acq_load(&ln->epoch) < e) { }
        float4 x0 = __ldcg(reinterpret_cast<const float4*>(&ln->h[0]));
        float4 x1 = __ldcg(reinterpret_cast<const float4*>(&ln->h[4]));
        float4 x2 = __ldcg(reinterpret_cast<const float4*>(&ln->h[8]));
        float4 x3 = __ldcg(reinterpret_cast<const float4*>(&ln->h[12]));
        float* d = smh + (tid >> 2) * HSTRIDE + (tid & 3) * 16;
        reinterpret_cast<float4*>(d)[0] = x0;
        reinterpret_cast<float4*>(d)[1] = x1;
        reinterpret_cast<float4*>(d)[2] = x2;
        reinterpret_cast<float4*>(d)[3] = x3;
    }
    __syncthreads();
}

// ---------------------------------------------------------------------------
__global__ void k_init() {
    int i = blockIdx.x * blockDim.x + threadIdx.x;
    if (i < 2 * NCTA) g_pub[i >> 7][i & 127].epoch = 0;
    if (i < NCTA * 32) g_flags[i] = 0;
}

// enc_w_hh (fp32, [6144][2048]) -> bf16, permuted: position p in row maps to
// source column col(p) = ((p>>3)&31)*64 + ((p>>8)<<3) + (p&7); rows CTA-major.
__global__ void k_convert(const float* __restrict__ whh) {
    size_t idx = (size_t)blockIdx.x * blockDim.x + threadIdx.x;
    if (idx >= (size_t)G3 * HDIM) return;
    int p   = (int)(idx & (HDIM - 1));
    int lrc = (int)(idx >> 11);
    int c   = lrc / ROWS_PC;
    int lr  = lrc - c * ROWS_PC;
    int g   = lr >> 4;
    int w   = lr & 15;
    int row = g * HDIM + c * JPC + w;
    int col = ((p >> 3) & 31) * 64 + ((p >> 8) << 3) + (p & 7);
    g_w16[idx] = __float2bfloat16(whh[(size_t)row * HDIM + col]);
}

// A[t, n] = sum_k X[t,k] * Wih[n,k] + b_ih[n] + (n < 2H ? b_hh[n] : 0)
__global__ void k_gemm(const float* __restrict__ X, const float* __restrict__ W,
                       const float* __restrict__ bih, const float* __restrict__ bhh,
                       int L) {
    __shared__ float As[16][65];
    __shared__ float Bs[16][65];
    int n0 = blockIdx.x * 64, t0 = blockIdx.y * 64;
    int tid = threadIdx.x;
    int tx = tid & 15, ty = tid >> 4;
    float acc[4][4];
#pragma unroll
    for (int i = 0; i < 4; i++)
#pragma unroll
        for (int jj = 0; jj < 4; jj++) acc[i][jj] = 0.f;

    for (int k0 = 0; k0 < IDIM; k0 += 16) {
#pragma unroll
        for (int i = 0; i < 4; i++) {
            int idx = tid + i * 256;
            int r = idx >> 4, cc = idx & 15;
            int t = t0 + r;
            As[cc][r] = (t < L) ? X[(size_t)t * IDIM + k0 + cc] : 0.f;
            Bs[cc][r] = W[(size_t)(n0 + r) * IDIM + k0 + cc];
        }
        __syncthreads();
#pragma unroll
        for (int kk = 0; kk < 16; kk++) {
            float a[4], b[4];
#pragma unroll
            for (int i = 0; i < 4; i++) a[i] = As[kk][ty * 4 + i];
#pragma unroll
            for (int jj = 0; jj < 4; jj++) b[jj] = Bs[kk][tx * 4 + jj];
#pragma unroll
            for (int i = 0; i < 4; i++)
#pragma unroll
                for (int jj = 0; jj < 4; jj++) acc[i][jj] = fmaf(a[i], b[jj], acc[i][jj]);
        }
        __syncthreads();
    }
#pragma unroll
    for (int i = 0; i < 4; i++) {
        int t = t0 + ty * 4 + i;
        if (t >= L) continue;
#pragma unroll
        for (int jj = 0; jj < 4; jj++) {
            int n = n0 + tx * 4 + jj;
            float v = acc[i][jj] + bih[n] + ((n < 2 * HDIM) ? bhh[n] : 0.f);
            g_A[(size_t)t * G3 + n] = v;
        }
    }
}

// ---------------------------------------------------------------------------
// Persistent RNN: 128 CTAs (1/SM), 1024 threads (32 warps). Warp pair
// (wr, wr+16) owns h element j = c*16 + wr; half hf covers h-columns
// lane*64 + hf*32 .. +31 as 16 f32x2 pairs in hp[].
__global__ void __launch_bounds__(NTH, 1)
k_rnn(const float* __restrict__ enc_bhh,
      const float* __restrict__ dwih, const float* __restrict__ dwhh,
      const float* __restrict__ dbih, const float* __restrict__ dbhh,
      const float* __restrict__ how,  const float* __restrict__ hob,
      float* __restrict__ out, int L, int T) {
    extern __shared__ unsigned short smw[];   // [48][2048] bf16 weights (permuted)
    float* smh = (float*)(smw + (size_t)ROWS_PC * HDIM);  // 32 chunks * 68 floats
    __shared__ float sPart[2][16][3];
    __shared__ float sGate[16];
    __shared__ float s_max, s_lse;
    __shared__ int   s_idx;

    const int c    = blockIdx.x;
    const int tid  = threadIdx.x;
    const int w    = tid >> 5;
    const int lane = tid & 31;
    const int wr   = w & 15;     // row group
    const int hf   = w >> 4;     // which half of h this warp covers
    const int j    = c * JPC + wr;

    // load this CTA's encoder weight slice into shared memory
    {
        const uint4* src = reinterpret_cast<const uint4*>(g_w16 + (size_t)c * ROWS_PC * HDIM);
        uint4* dst = reinterpret_cast<uint4*>(smw);
        for (int i = tid; i < ROWS_PC * HDIM / 8; i += NTH) dst[i] = src[i];
    }

    unsigned long long hp[16];            // f32x2 pairs of h[lane*64 + hf*32 + 2i]
#pragma unroll
    for (int i = 0; i < 16; i++) hp[i] = 0ull;
    float hold = 0.f;                     // low-warp lane0: current h[j]
    float bhn  = enc_bhh[2 * HDIM + j];
    int epoch = 0;
    // prefetch A for t=0
    float pAr = 0.f, pAz = 0.f, pAn = 0.f;
    if (hf == 0 && lane == 0 && L > 0) {
        const float* Ab = g_A + j;
        pAr = __ldg(Ab); pAz = __ldg(Ab + HDIM); pAn = __ldg(Ab + 2 * HDIM);
    }
    __syncthreads();

    // ---------------- encoder: L sequential GRU steps ----------------
    for (int t = 0; t < L; t++) {
        float Ar = pAr, Az = pAz, An = pAn;
        if (hf == 0 && lane == 0 && t + 1 < L) {   // prefetch next step's A now
            const float* Ab = g_A + (size_t)(t + 1) * G3 + j;
            pAr = __ldg(Ab); pAz = __ldg(Ab + HDIM); pAn = __ldg(Ab + 2 * HDIM);
        }
        const unsigned short* wbase = smw + hf * 1024;
#pragma unroll
        for (int g = 0; g < 3; g++) {
            const unsigned short* wrow = wbase + (size_t)(g * JPC + wr) * HDIM;
            unsigned long long s0 = 0ull, s1 = 0ull, s2 = 0ull, s3 = 0ull;
#pragma unroll
            for (int c8 = 0; c8 < 4; c8++) {
                uint4 p = *reinterpret_cast<const uint4*>(wrow + c8 * 256 + lane * 8);
                s0 = ffma2(bf16pair(p.x), hp[c8 * 4 + 0], s0);
                s1 = ffma2(bf16pair(p.y), hp[c8 * 4 + 1], s1);
                s2 = ffma2(bf16pair(p.z), hp[c8 * 4 + 2], s2);
                s3 = ffma2(bf16pair(p.w), hp[c8 * 4 + 3], s3);
            }
            float2 f0 = unpack2(s0), f1 = unpack2(s1), f2 = unpack2(s2), f3 = unpack2(s3);
            float sum = ((f0.x + f0.y) + (f1.x + f1.y)) + ((f2.x + f2.y) + (f3.x + f3.y));
            float s = warp_sum(sum);
            if (lane == 0) sPart[hf][wr][g] = s;
        }
        __syncthreads();
        if (hf == 0 && lane == 0) {
            float dr = sPart[0][wr][0] + sPart[1][wr][0];
            float dz = sPart[0][wr][1] + sPart[1][wr][1];
            float dn = sPart[0][wr][2] + sPart[1][wr][2];
            float r = fast_sigmoid(dr + Ar);
            float z = fast_sigmoid(dz + Az);
            float n = fast_tanh(An + r * (dn + bhn));
            hold = (1.f - z) * n + z * hold;
            sGate[wr] = hold;
        }
        epoch++;
        publish_barrier(epoch, c, tid, smh, sGate);
#pragma unroll
        for (int i4 = 0; i4 < 8; i4++) {
            float4 v = *reinterpret_cast<const float4*>(smh + lane * HSTRIDE + hf * 32 + i4 * 4);
            hp[i4 * 2 + 0] = pack2(v.x, v.y);
            hp[i4 * 2 + 1] = pack2(v.z, v.w);
        }
    }

    // ---------------- autoregressive decoder ----------------
    float bir = 0.f, biz = 0.f, bin = 0.f, bhnd = 0.f;
    if (hf == 0 && lane == 0) {
        bir  = dbih[j] + dbhh[j];
        biz  = dbih[HDIM + j] + dbhh[HDIM + j];
        bin  = dbih[2 * HDIM + j];
        bhnd = dbhh[2 * HDIM + j];
    }
    int idx = -1;   // one-hot index; -1 means zero input (first step)
    const float* hbase = smh + lane * HSTRIDE + hf * 32;   // this warp's h slice

    for (int s = 0; s < T; s++) {
        // --- phase A: GRU step (fp32 weights from L2; h read from smh) ---
#pragma unroll
        for (int g = 0; g < 3; g++) {
            const float* wrow = dwhh + (size_t)(g * HDIM + j) * HDIM + hf * 32;
            float a0 = 0.f, a1 = 0.f, a2 = 0.f, a3 = 0.f;
#pragma unroll
            for (int c8 = 0; c8 < 4; c8++) {
                const float4* p = reinterpret_cast<const float4*>(wrow + lane * 64 + c8 * 8);
                float4 v0 = __ldg(p);
                float4 v1 = __ldg(p + 1);
                float4 h0 = *reinterpret_cast<const float4*>(hbase + c8 * 8);
                float4 h1 = *reinterpret_cast<const float4*>(hbase + c8 * 8 + 4);
                a0 = fmaf(v0.x, h0.x, a0);
                a1 = fmaf(v0.y, h0.y, a1);
                a2 = fmaf(v0.z, h0.z, a2);
                a3 = fmaf(v0.w, h0.w, a3);
                a0 = fmaf(v1.x, h1.x, a0);
                a1 = fmaf(v1.y, h1.y, a1);
                a2 = fmaf(v1.z, h1.z, a2);
                a3 = fmaf(v1.w, h1.w, a3);
            }
            float ssum = warp_sum((a0 + a1) + (a2 + a3));
            if (lane == 0) sPart[hf][wr][g] = ssum;
        }
        __syncthreads();
        if (hf == 0 && lane == 0) {
            float gr = bir, gz = biz, gn = bin;
            if (idx >= 0) {   // one-hot input -> column gather of dec_w_ih
                gr += __ldg(dwih + (size_t)j * ODIM + idx);
                gz += __ldg(dwih + (size_t)(HDIM + j) * ODIM + idx);
                gn += __ldg(dwih + (size_t)(2 * HDIM + j) * ODIM + idx);
            }
            float dr = sPart[0][wr][0] + sPart[1][wr][0];
            float dz = sPart[0][wr][1] + sPart[1][wr][1];
            float dn = sPart[0][wr][2] + sPart[1][wr][2];
            float r = fast_sigmoid(dr + gr);
            float z = fast_sigmoid(dz + gz);
            float n = fast_tanh(gn + r * (dn + bhnd));
            hold = (1.f - z) * n + z * hold;
            sGate[wr] = hold;
        }
        epoch++;
        publish_barrier(epoch, c, tid, smh, sGate);   // smh now holds h_new
        // --- phase B: logits = h_new @ h2o_w^T + b (4 rows/CTA, warps 0-3) ---
        float mylogit = 0.f;
        if (w < 4) {
            int row = c * 4 + w;
            const float* wrow = how + (size_t)row * HDIM;
            float a0 = 0.f, a1 = 0.f, a2 = 0.f, a3 = 0.f;
#pragma unroll
            for (int c8 = 0; c8 < 8; c8++) {
                const float4* p = reinterpret_cast<const float4*>(wrow + lane * 64 + c8 * 8);
                float4 v0 = __ldg(p);
                float4 v1 = __ldg(p + 1);
                const float* hpt = smh + lane * HSTRIDE + c8 * 8;
                float4 h0 = *reinterpret_cast<const float4*>(hpt);
                float4 h1 = *reinterpret_cast<const float4*>(hpt + 4);
                a0 = fmaf(v0.x, h0.x, a0);
                a1 = fmaf(v0.y, h0.y, a1);
                a2 = fmaf(v0.z, h0.z, a2);
                a3 = fmaf(v0.w, h0.w, a3);
                a0 = fmaf(v1.x, h1.x, a0);
                a1 = fmaf(v1.y, h1.y, a1);
                a2 = fmaf(v1.z, h1.z, a2);
                a3 = fmaf(v1.w, h1.w, a3);
            }
            float acc = warp_sum((a0 + a1) + (a2 + a3));
            if (lane == 0) {
                mylogit = acc + __ldg(hob + row);
                g_logits[row] = mylogit;
            }
        }
        epoch++;
        grid_barrier(epoch, c, tid, lane);
        // --- phase C: softmax stats + argmax (redundant per CTA, deterministic) ---
        if (w == 0) {
            float v[16];
#pragma unroll
            for (int q = 0; q < 16; q++) v[q] = __ldcg(g_logits + q * 32 + lane);
            float mx = v[0]; int mi = lane;
#pragma unroll
            for (int q = 1; q < 16; q++)
                if (v[q] > mx) { mx = v[q]; mi = q * 32 + lane; }
#pragma unroll
            for (int off = 16; off; off >>= 1) {
                float om = __shfl_xor_sync(0xffffffffu, mx, off);
                int   oi = __shfl_xor_sync(0xffffffffu, mi, off);
                if (om > mx || (om == mx && oi < mi)) { mx = om; mi = oi; }
            }
            float se = 0.f;
#pragma unroll
            for (int q = 0; q < 16; q++) se += expf(v[q] - mx);
            se = warp_sum(se);
            if (lane == 0) { s_max = mx; s_lse = logf(se); s_idx = mi; }
        }
        __syncthreads();
        idx = s_idx;
        if (w < 4 && lane == 0)
            out[(size_t)s * ODIM + c * 4 + w] = mylogit - s_max - s_lse;
        epoch++;
        grid_barrier(epoch, c, tid, lane);   // protect g_logits reuse next step
    }
}

// ---------------------------------------------------------------------------
extern "C" void kernel_launch(void* const* d_in, const int* in_sizes, int n_in,
                              void* d_out, int out_size) {
    const float* input_   = (const float*)d_in[0];
    const float* enc_w_ih = (const float*)d_in[1];
    const float* enc_w_hh = (const float*)d_in[2];
    const float* enc_b_ih = (const float*)d_in[3];
    const float* enc_b_hh = (const float*)d_in[4];
    const float* dec_w_ih = (const float*)d_in[5];
    const float* dec_w_hh = (const float*)d_in[6];
    const float* dec_b_ih = (const float*)d_in[7];
    const float* dec_b_hh = (const float*)d_in[8];
    const float* h2o_w    = (const float*)d_in[9];
    const float* h2o_b    = (const float*)d_in[10];

    int L = in_sizes[0] / IDIM;
    if (L > MAXL) L = MAXL;
    int T = out_size / ODIM;

    const int dyn_smem = ROWS_PC * HDIM * (int)sizeof(unsigned short)
                       + 32 * HSTRIDE * (int)sizeof(float);
    cudaFuncSetAttribute(k_rnn, cudaFuncAttributeMaxDynamicSharedMemorySize, dyn_smem);

    k_init<<<16, 256>>>();
    {
        size_t total = (size_t)G3 * HDIM;
        int grid = (int)((total + 255) / 256);
        k_convert<<<grid, 256>>>(enc_w_hh);
    }
    {
        dim3 gg(G3 / 64, (L + 63) / 64);
        k_gemm<<<gg, 256>>>(input_, enc_w_ih, enc_b_ih, enc_b_hh, L);
    }
    k_rnn<<<NCTA, NTH, dyn_smem>>>(
        enc_b_hh, dec_w_ih, dec_w_hh, dec_b_ih, dec_b_hh,
        h2o_w, h2o_b, (float*)d_out, L, T);
}